// round 13
// baseline (speedup 1.0000x reference)
#include <cuda_runtime.h>
#include <cuda_fp16.h>
#include <stdint.h>

#define DM 768
#define DI 1536
#define DS 16
#define LSEQ 1024
#define NL 4
#define NV 32000

// ---------------- fp32 scratch ----------------
__device__ float g_x [LSEQ * DM];
__device__ float g_xn[LSEQ * DM];
__device__ float g_xz[LSEQ * 2 * DI];
__device__ float g_xc[LSEQ * DI];
__device__ float g_xp[LSEQ * 33];
__device__ float g_y [LSEQ * DI];

// ---------------- fp16 operands ----------------
__device__ __half g_eb[NV * DM];
__device__ __half g_wi[NL * 2 * DI * DM];
__device__ __half g_wo[NL * DM * DI];
__device__ __half g_a [LSEQ * DI];

// ======================= helpers =======================
__device__ __forceinline__ uint32_t smem_u32(const void* p) {
    uint32_t a;
    asm("{ .reg .u64 t; cvta.to.shared.u64 t, %1; cvt.u32.u64 %0, t; }" : "=r"(a) : "l"(p));
    return a;
}
__device__ __forceinline__ void cp_async16(uint32_t saddr, const void* gaddr) {
    asm volatile("cp.async.cg.shared.global [%0], [%1], 16;" :: "r"(saddr), "l"(gaddr));
}
__device__ __forceinline__ void cp_commit() {
    asm volatile("cp.async.commit_group;" ::: "memory");
}
__device__ __forceinline__ void cp_wait2() {
    asm volatile("cp.async.wait_group 2;" ::: "memory");
}
__device__ __forceinline__ void mma16816(float* c, const uint32_t* a, const uint32_t* b) {
    asm volatile("mma.sync.aligned.m16n8k16.row.col.f32.f16.f16.f32 "
                 "{%0,%1,%2,%3}, {%4,%5,%6,%7}, {%8,%9}, {%0,%1,%2,%3};"
                 : "+f"(c[0]), "+f"(c[1]), "+f"(c[2]), "+f"(c[3])
                 : "r"(a[0]), "r"(a[1]), "r"(a[2]), "r"(a[3]), "r"(b[0]), "r"(b[1]));
}
__device__ __forceinline__ void ldsm4(uint32_t& r0, uint32_t& r1, uint32_t& r2, uint32_t& r3,
                                      uint32_t saddr) {
    asm volatile("ldmatrix.sync.aligned.m8n8.x4.shared.b16 {%0,%1,%2,%3}, [%4];"
                 : "=r"(r0), "=r"(r1), "=r"(r2), "=r"(r3) : "r"(saddr));
}

// ======================= convert fp32 -> fp16 =======================
__global__ void cvt4(const float4* __restrict__ src, __half2* __restrict__ dst, int n4) {
    int i = blockIdx.x * blockDim.x + threadIdx.x;
    if (i >= n4) return;
    float4 v = src[i];
    dst[2 * i]     = __floats2half2_rn(v.x, v.y);
    dst[2 * i + 1] = __floats2half2_rn(v.z, v.w);
}

// ======================= mma.sync GEMM (single-pass fp16) =======================
// C[M,N] = A[M,K] @ B[N,K]^T (+ add).
// Block tile 128x128, K-stage 32, 4-stage cp.async ring (prefetch depth 2).
// 256 threads = 8 warps (2x4); each warp computes 64x32. 2 CTAs/SM.
#define ROWP 40                       // padded row stride (elements); 80 bytes
#define OPSZ (128 * ROWP)             // one operand tile (elements)
#define STAGE_E (2 * OPSZ)            // A, B
#define NSTG 4
#define GSMEM_B (NSTG * STAGE_E * 2)  // 81920 bytes

__global__ __launch_bounds__(256, 2)
void gemm_tc(const __half* __restrict__ A, const __half* __restrict__ B,
             float* __restrict__ C, const float* __restrict__ add, int N, int K) {
    extern __shared__ __half sm[];
    uint32_t sb = smem_u32(sm);
    int tid = threadIdx.x;
    int wid = tid >> 5, lane = tid & 31;
    int warp_m = wid >> 2, warp_n = wid & 3;     // 2 x 4
    int quad = lane >> 3, lr = lane & 7;
    int m0 = blockIdx.y * 128, n0 = blockIdx.x * 128;

    const __half* gA = A + (size_t)m0 * K;
    const __half* gB = B + (size_t)n0 * K;
    int nst = K >> 5;  // K/32

    auto load_stage = [&](int ks) {
        int k0 = ks << 5;
        uint32_t sbase = sb + (uint32_t)(ks & (NSTG - 1)) * (STAGE_E * 2);
#pragma unroll
        for (int c = 0; c < 4; c++) {
            int ch  = tid + c * 256;          // 0..1023
            int op  = ch >> 9;                // 0=A, 1=B
            int idx = ch & 511;
            int row = idx >> 2, q = idx & 3;
            const __half* g = (op == 0) ? gA : gB;
            cp_async16(sbase + (uint32_t)(op * OPSZ + row * ROWP + q * 8) * 2,
                       g + (size_t)row * K + k0 + q * 8);
        }
    };

    // per-lane ldmatrix row/col offsets
    int rA = (quad & 1) * 8 + lr, cAo = (quad >> 1) * 8;
    int rB = (quad >> 1) * 8 + lr, cBo = (quad & 1) * 8;

    float acc[4][4][4] = {};

    load_stage(0); cp_commit();
    load_stage(1); cp_commit();

    for (int ks = 0; ks < nst; ks++) {
        if (ks + 2 < nst) load_stage(ks + 2);
        cp_commit();
        cp_wait2();
        __syncthreads();

        uint32_t st = sb + (uint32_t)(ks & (NSTG - 1)) * (STAGE_E * 2);
        uint32_t aS = st;
        uint32_t bS = st + OPSZ * 2;

#pragma unroll
        for (int kk = 0; kk < 32; kk += 16) {
            uint32_t af[4][4], bf[4][2];
#pragma unroll
            for (int mt = 0; mt < 4; mt++) {
                uint32_t off = (uint32_t)((warp_m * 64 + mt * 16 + rA) * ROWP + kk + cAo) * 2;
                ldsm4(af[mt][0], af[mt][1], af[mt][2], af[mt][3], aS + off);
            }
#pragma unroll
            for (int p = 0; p < 2; p++) {
                uint32_t off = (uint32_t)((warp_n * 32 + p * 16 + rB) * ROWP + kk + cBo) * 2;
                ldsm4(bf[2 * p][0], bf[2 * p][1], bf[2 * p + 1][0], bf[2 * p + 1][1], bS + off);
            }
#pragma unroll
            for (int mt = 0; mt < 4; mt++)
#pragma unroll
                for (int nt = 0; nt < 4; nt++) mma16816(acc[mt][nt], af[mt], bf[nt]);
        }
    }

    __syncthreads();
    // ---- epilogue ----
    int g = lane >> 2, tg = lane & 3;
#pragma unroll
    for (int mt = 0; mt < 4; mt++)
#pragma unroll
        for (int nt = 0; nt < 4; nt++) {
            int m = m0 + warp_m * 64 + mt * 16 + g;
            int n = n0 + warp_n * 32 + nt * 8 + tg * 2;
            float* c = acc[mt][nt];
            size_t o0 = (size_t)m * N + n;
            size_t o1 = (size_t)(m + 8) * N + n;
            if (add) {
                c[0] += add[o0]; c[1] += add[o0 + 1];
                c[2] += add[o1]; c[3] += add[o1 + 1];
            }
            *(float2*)(C + o0) = make_float2(c[0], c[1]);
            *(float2*)(C + o1) = make_float2(c[2], c[3]);
        }
}

// ======================= elementwise / scan kernels =======================
__global__ void embed_gather(const int* __restrict__ idx, const float* __restrict__ embed) {
    int t = blockIdx.x;
    int row = idx[t];
    const float4* src = (const float4*)(embed + (size_t)row * DM);
    float4* dst = (float4*)(g_x + t * DM);
    for (int i = threadIdx.x; i < DM / 4; i += blockDim.x) dst[i] = src[i];
}

__global__ void rmsnorm_k(const float* __restrict__ in, const float* __restrict__ w,
                          float* __restrict__ out, int D) {
    int t = blockIdx.x;
    __shared__ float red[32];
    float s = 0.f;
    for (int i = threadIdx.x; i < D; i += blockDim.x) {
        float v = in[t * D + i];
        s += v * v;
    }
    for (int o = 16; o; o >>= 1) s += __shfl_xor_sync(~0u, s, o);
    if ((threadIdx.x & 31) == 0) red[threadIdx.x >> 5] = s;
    __syncthreads();
    if (threadIdx.x < 32) {
        float v = (threadIdx.x < (blockDim.x >> 5)) ? red[threadIdx.x] : 0.f;
        for (int o = 16; o; o >>= 1) v += __shfl_xor_sync(~0u, v, o);
        if (threadIdx.x == 0) red[0] = rsqrtf(v / (float)D + 1e-5f);
    }
    __syncthreads();
    float inv = red[0];
    for (int i = threadIdx.x; i < D; i += blockDim.x)
        out[t * D + i] = in[t * D + i] * inv * w[i];
}

__global__ void conv_silu(const float* __restrict__ cw, const float* __restrict__ cb) {
    int idx = blockIdx.x * blockDim.x + threadIdx.x;
    if (idx >= LSEQ * DI) return;
    int d = idx % DI, t = idx / DI;
    float s = cb[d];
#pragma unroll
    for (int j = 0; j < 4; j++) {
        int tt = t - 3 + j;
        if (tt >= 0) s += g_xz[tt * (2 * DI) + d] * cw[d * 4 + j];
    }
    float sig = 1.f / (1.f + __expf(-s));
    g_xc[idx] = s * sig;
}

__global__ __launch_bounds__(256)
void xproj(const float* __restrict__ Wx) {
    int t = blockIdx.x;
    __shared__ float row[DI];
    for (int i = threadIdx.x; i < DI; i += blockDim.x)
        row[i] = g_xc[t * DI + i];
    __syncthreads();
    int wid = threadIdx.x >> 5, lane = threadIdx.x & 31;
    for (int j = wid; j < 33; j += 8) {
        const float* wr = Wx + j * DI;
        float s = 0.f;
        for (int k = lane; k < DI; k += 32) s += row[k] * wr[k];
        for (int o = 16; o; o >>= 1) s += __shfl_xor_sync(~0u, s, o);
        if (lane == 0) g_xp[t * 33 + j] = s;
    }
}

__global__ __launch_bounds__(256)
void scan_k(const float* __restrict__ dt_w, const float* __restrict__ dt_b,
            const float* __restrict__ A_log, const float* __restrict__ Dp) {
    int gw = (blockIdx.x * blockDim.x + threadIdx.x) >> 5;
    int lane = threadIdx.x & 31;
    int d = gw * 2 + (lane >> 4);
    int n = lane & 15;
    if (d >= DI) return;

    float Av  = -__expf(A_log[d * DS + n]);
    float dtw = dt_w[d];
    float dtb = dt_b[d];
    float Dv  = Dp[d];
    float h = 0.f;

    for (int t = 0; t < LSEQ; t++) {
        const float* xpr = g_xp + t * 33;
        float dtr = __ldg(xpr);
        float Bn  = __ldg(xpr + 1 + n);
        float Cn  = __ldg(xpr + 17 + n);
        float xcv = g_xc[t * DI + d];

        float xdt = fmaf(dtr, dtw, dtb);
        float dt  = (xdt > 20.f) ? xdt : log1pf(__expf(xdt));
        float dA  = __expf(dt * Av);
        h = fmaf(dA, h, dt * Bn * xcv);

        float p = h * Cn;
        p += __shfl_xor_sync(~0u, p, 8);
        p += __shfl_xor_sync(~0u, p, 4);
        p += __shfl_xor_sync(~0u, p, 2);
        p += __shfl_xor_sync(~0u, p, 1);

        if (n == 0) {
            float y = p + xcv * Dv;
            float z = g_xz[t * 2 * DI + DI + d];
            float zs = z / (1.f + __expf(-z));
            g_y[t * DI + d] = y * zs;
        }
    }
}

// ======================= host launcher =======================
extern "C" void kernel_launch(void* const* d_in, const int* in_sizes, int n_in,
                              void* d_out, int out_size) {
    const int*   idx      = (const int*)  d_in[0];
    const float* embed    = (const float*)d_in[1];
    const float* norm_w   = (const float*)d_in[2];
    const float* W_in     = (const float*)d_in[3];
    const float* conv_w   = (const float*)d_in[4];
    const float* conv_b   = (const float*)d_in[5];
    const float* W_x      = (const float*)d_in[6];
    const float* dt_w     = (const float*)d_in[7];
    const float* dt_b     = (const float*)d_in[8];
    const float* A_log    = (const float*)d_in[9];
    const float* Dp       = (const float*)d_in[10];
    const float* out_w    = (const float*)d_in[11];
    const float* norm_f_w = (const float*)d_in[12];
    float* out = (float*)d_out;

    float *px, *pxn, *pxz, *py;
    cudaGetSymbolAddress((void**)&px,  g_x);
    cudaGetSymbolAddress((void**)&pxn, g_xn);
    cudaGetSymbolAddress((void**)&pxz, g_xz);
    cudaGetSymbolAddress((void**)&py,  g_y);
    __half *eb, *wi, *wo, *ac;
    cudaGetSymbolAddress((void**)&eb, g_eb);
    cudaGetSymbolAddress((void**)&wi, g_wi);
    cudaGetSymbolAddress((void**)&wo, g_wo);
    cudaGetSymbolAddress((void**)&ac, g_a);

    static bool attr_set = false;
    if (!attr_set) {
        cudaFuncSetAttribute(gemm_tc, cudaFuncAttributeMaxDynamicSharedMemorySize, GSMEM_B);
        attr_set = true;
    }

    // operand converts (deterministic, graph-capturable)
    {
        int n4 = NV * DM / 4;
        cvt4<<<(n4 + 255) / 256, 256>>>((const float4*)embed, (__half2*)eb, n4);
        n4 = NL * 2 * DI * DM / 4;
        cvt4<<<(n4 + 255) / 256, 256>>>((const float4*)W_in, (__half2*)wi, n4);
        n4 = NL * DM * DI / 4;
        cvt4<<<(n4 + 255) / 256, 256>>>((const float4*)out_w, (__half2*)wo, n4);
    }

    embed_gather<<<LSEQ, 192>>>(idx, embed);

    for (int l = 0; l < NL; l++) {
        rmsnorm_k<<<LSEQ, 256>>>(px, norm_w + l * DM, pxn, DM);

        {
            int n4 = LSEQ * DM / 4;
            cvt4<<<(n4 + 255) / 256, 256>>>((const float4*)pxn, (__half2*)ac, n4);
        }
        dim3 g1(2 * DI / 128, LSEQ / 128);
        gemm_tc<<<g1, 256, GSMEM_B>>>(ac, wi + (size_t)l * 2 * DI * DM,
                                      pxz, nullptr, 2 * DI, DM);

        conv_silu<<<(LSEQ * DI + 255) / 256, 256>>>(conv_w + l * DI * 4, conv_b + l * DI);
        xproj<<<LSEQ, 256>>>(W_x + l * 33 * DI);
        scan_k<<<(DI / 2 + 7) / 8, 256>>>(dt_w + l * DI, dt_b + l * DI,
                                          A_log + l * DI * DS, Dp + l * DI);

        {
            int n4 = LSEQ * DI / 4;
            cvt4<<<(n4 + 255) / 256, 256>>>((const float4*)py, (__half2*)ac, n4);
        }
        dim3 g2(DM / 128, LSEQ / 128);
        gemm_tc<<<g2, 256, GSMEM_B>>>(ac, wo + (size_t)l * DM * DI,
                                      px, px, DM, DI);
    }

    rmsnorm_k<<<LSEQ, 256>>>(px, norm_f_w, pxn, DM);
    {
        int n4 = LSEQ * DM / 4;
        cvt4<<<(n4 + 255) / 256, 256>>>((const float4*)pxn, (__half2*)ac, n4);
    }
    dim3 g3(NV / 128, LSEQ / 128);
    gemm_tc<<<g3, 256, GSMEM_B>>>(ac, eb, out, nullptr, NV, DM);
}

// round 14
// speedup vs baseline: 2.2948x; 2.2948x over previous
#include <cuda_runtime.h>
#include <cuda_fp16.h>
#include <stdint.h>

#define DM 768
#define DI 1536
#define DS 16
#define LSEQ 1024
#define NL 4
#define NV 32000
#define NC 8
#define TC (LSEQ / NC)

// ---------------- fp32 scratch ----------------
__device__ float g_x [LSEQ * DM];        // residual stream
__device__ float g_xz[LSEQ * 2 * DI];    // in-proj output (x_ssm | z)
__device__ float g_xc[LSEQ * DI];        // conv+silu output
__device__ float g_xp[LSEQ * 33];        // x-proj output (dt_r | B | C)
// scan chunk scratch
__device__ float g_hend[NC * DI * DS];
__device__ float g_h0  [NC * DI * DS];
__device__ float g_dts [NC * DI];

// ---------------- fp16 operands ----------------
__device__ __half g_eb[NV * DM];
__device__ __half g_wi[NL * 2 * DI * DM];
__device__ __half g_wo[NL * DM * DI];
__device__ __half g_a [LSEQ * DI];       // GEMM A operand (rows of K elems)

// ======================= helpers =======================
__device__ __forceinline__ uint32_t smem_u32(const void* p) {
    uint32_t a;
    asm("{ .reg .u64 t; cvta.to.shared.u64 t, %1; cvt.u32.u64 %0, t; }" : "=r"(a) : "l"(p));
    return a;
}
__device__ __forceinline__ void cp_async16(uint32_t saddr, const void* gaddr) {
    asm volatile("cp.async.cg.shared.global [%0], [%1], 16;" :: "r"(saddr), "l"(gaddr));
}
__device__ __forceinline__ void cp_commit() {
    asm volatile("cp.async.commit_group;" ::: "memory");
}
__device__ __forceinline__ void cp_wait2() {
    asm volatile("cp.async.wait_group 2;" ::: "memory");
}
__device__ __forceinline__ void mma16816(float* c, const uint32_t* a, const uint32_t* b) {
    asm volatile("mma.sync.aligned.m16n8k16.row.col.f32.f16.f16.f32 "
                 "{%0,%1,%2,%3}, {%4,%5,%6,%7}, {%8,%9}, {%0,%1,%2,%3};"
                 : "+f"(c[0]), "+f"(c[1]), "+f"(c[2]), "+f"(c[3])
                 : "r"(a[0]), "r"(a[1]), "r"(a[2]), "r"(a[3]), "r"(b[0]), "r"(b[1]));
}
__device__ __forceinline__ void ldsm4(uint32_t& r0, uint32_t& r1, uint32_t& r2, uint32_t& r3,
                                      uint32_t saddr) {
    asm volatile("ldmatrix.sync.aligned.m8n8.x4.shared.b16 {%0,%1,%2,%3}, [%4];"
                 : "=r"(r0), "=r"(r1), "=r"(r2), "=r"(r3) : "r"(saddr));
}

// ======================= convert fp32 -> fp16 =======================
__global__ void cvt4(const float4* __restrict__ src, __half2* __restrict__ dst, int n4) {
    int i = blockIdx.x * blockDim.x + threadIdx.x;
    if (i >= n4) return;
    float4 v = src[i];
    dst[2 * i]     = __floats2half2_rn(v.x, v.y);
    dst[2 * i + 1] = __floats2half2_rn(v.z, v.w);
}

// ======================= mma.sync GEMM (fp16, fp32 acc) =======================
// C[M,N] = A[M,K] @ B[N,K]^T (+ add).
// 128x128 tile, K-stage 32, 4-buffer cp.async ring, prefetch depth 3.
// 256 threads = 8 warps (2x4); each warp computes 64x32. occ 1 (no reg clamp).
#define ROWP 40                       // padded row stride (elements); 80 bytes
#define OPSZ (128 * ROWP)
#define STAGE_E (2 * OPSZ)            // A, B
#define NSTG 4
#define GSMEM_B (NSTG * STAGE_E * 2)  // 81920 bytes

__global__ __launch_bounds__(256)
void gemm_tc(const __half* __restrict__ A, const __half* __restrict__ B,
             float* __restrict__ C, const float* __restrict__ add, int N, int K) {
    extern __shared__ __half sm[];
    uint32_t sb = smem_u32(sm);
    int tid = threadIdx.x;
    int wid = tid >> 5, lane = tid & 31;
    int warp_m = wid >> 2, warp_n = wid & 3;     // 2 x 4
    int quad = lane >> 3, lr = lane & 7;
    int m0 = blockIdx.y * 128, n0 = blockIdx.x * 128;

    const __half* gA = A + (size_t)m0 * K;
    const __half* gB = B + (size_t)n0 * K;
    int nst = K >> 5;  // K/32

    auto load_stage = [&](int ks) {
        int k0 = ks << 5;
        uint32_t sbase = sb + (uint32_t)(ks & (NSTG - 1)) * (STAGE_E * 2);
#pragma unroll
        for (int c = 0; c < 4; c++) {
            int ch  = tid + c * 256;          // 0..1023
            int op  = ch >> 9;                // 0=A, 1=B
            int idx = ch & 511;
            int row = idx >> 2, q = idx & 3;
            const __half* g = (op == 0) ? gA : gB;
            cp_async16(sbase + (uint32_t)(op * OPSZ + row * ROWP + q * 8) * 2,
                       g + (size_t)row * K + k0 + q * 8);
        }
    };

    int rA = (quad & 1) * 8 + lr, cAo = (quad >> 1) * 8;
    int rB = (quad >> 1) * 8 + lr, cBo = (quad & 1) * 8;

    float acc[4][4][4] = {};

    load_stage(0); cp_commit();
    load_stage(1); cp_commit();
    load_stage(2); cp_commit();

    for (int ks = 0; ks < nst; ks++) {
        cp_wait2();
        __syncthreads();
        // safe: all threads are past compute(ks-1); buffer (ks+3)&3 is free
        if (ks + 3 < nst) load_stage(ks + 3);
        cp_commit();

        uint32_t st = sb + (uint32_t)(ks & (NSTG - 1)) * (STAGE_E * 2);
        uint32_t aS = st;
        uint32_t bS = st + OPSZ * 2;

#pragma unroll
        for (int kk = 0; kk < 32; kk += 16) {
            uint32_t af[4][4], bf[4][2];
#pragma unroll
            for (int mt = 0; mt < 4; mt++) {
                uint32_t off = (uint32_t)((warp_m * 64 + mt * 16 + rA) * ROWP + kk + cAo) * 2;
                ldsm4(af[mt][0], af[mt][1], af[mt][2], af[mt][3], aS + off);
            }
#pragma unroll
            for (int p = 0; p < 2; p++) {
                uint32_t off = (uint32_t)((warp_n * 32 + p * 16 + rB) * ROWP + kk + cBo) * 2;
                ldsm4(bf[2 * p][0], bf[2 * p][1], bf[2 * p + 1][0], bf[2 * p + 1][1], bS + off);
            }
#pragma unroll
            for (int mt = 0; mt < 4; mt++)
#pragma unroll
                for (int nt = 0; nt < 4; nt++) mma16816(acc[mt][nt], af[mt], bf[nt]);
        }
    }

    __syncthreads();
    int g = lane >> 2, tg = lane & 3;
#pragma unroll
    for (int mt = 0; mt < 4; mt++)
#pragma unroll
        for (int nt = 0; nt < 4; nt++) {
            int m = m0 + warp_m * 64 + mt * 16 + g;
            int n = n0 + warp_n * 32 + nt * 8 + tg * 2;
            float* c = acc[mt][nt];
            size_t o0 = (size_t)m * N + n;
            size_t o1 = (size_t)(m + 8) * N + n;
            if (add) {
                c[0] += add[o0]; c[1] += add[o0 + 1];
                c[2] += add[o1]; c[3] += add[o1 + 1];
            }
            *(float2*)(C + o0) = make_float2(c[0], c[1]);
            *(float2*)(C + o1) = make_float2(c[2], c[3]);
        }
}

// ======================= fused embed + rmsnorm (layer 0) =======================
__global__ void embed_rms(const int* __restrict__ idx, const float* __restrict__ embed,
                          const float* __restrict__ w) {
    int t = blockIdx.x;
    int row = idx[t];
    const float* src = embed + (size_t)row * DM;
    __shared__ float red[32];
    float s = 0.f;
    for (int i = threadIdx.x; i < DM; i += blockDim.x) {
        float v = src[i];
        g_x[t * DM + i] = v;
        s += v * v;
    }
    for (int o = 16; o; o >>= 1) s += __shfl_xor_sync(~0u, s, o);
    if ((threadIdx.x & 31) == 0) red[threadIdx.x >> 5] = s;
    __syncthreads();
    if (threadIdx.x < 32) {
        float v = (threadIdx.x < (blockDim.x >> 5)) ? red[threadIdx.x] : 0.f;
        for (int o = 16; o; o >>= 1) v += __shfl_xor_sync(~0u, v, o);
        if (threadIdx.x == 0) red[0] = rsqrtf(v / (float)DM + 1e-5f);
    }
    __syncthreads();
    float inv = red[0];
    for (int i = threadIdx.x; i < DM; i += blockDim.x)
        g_a[t * DM + i] = __float2half(src[i] * inv * w[i]);
}

// rmsnorm from g_x -> fp16 g_a
__global__ void rmsnorm_h(const float* __restrict__ in, const float* __restrict__ w) {
    int t = blockIdx.x;
    __shared__ float red[32];
    float s = 0.f;
    for (int i = threadIdx.x; i < DM; i += blockDim.x) {
        float v = in[t * DM + i];
        s += v * v;
    }
    for (int o = 16; o; o >>= 1) s += __shfl_xor_sync(~0u, s, o);
    if ((threadIdx.x & 31) == 0) red[threadIdx.x >> 5] = s;
    __syncthreads();
    if (threadIdx.x < 32) {
        float v = (threadIdx.x < (blockDim.x >> 5)) ? red[threadIdx.x] : 0.f;
        for (int o = 16; o; o >>= 1) v += __shfl_xor_sync(~0u, v, o);
        if (threadIdx.x == 0) red[0] = rsqrtf(v / (float)DM + 1e-5f);
    }
    __syncthreads();
    float inv = red[0];
    for (int i = threadIdx.x; i < DM; i += blockDim.x)
        g_a[t * DM + i] = __float2half(in[t * DM + i] * inv * w[i]);
}

// ======================= conv / xproj =======================
__global__ void conv_silu(const float* __restrict__ cw, const float* __restrict__ cb) {
    int idx = blockIdx.x * blockDim.x + threadIdx.x;
    if (idx >= LSEQ * DI) return;
    int d = idx % DI, t = idx / DI;
    float s = cb[d];
#pragma unroll
    for (int j = 0; j < 4; j++) {
        int tt = t - 3 + j;
        if (tt >= 0) s += g_xz[tt * (2 * DI) + d] * cw[d * 4 + j];
    }
    float sig = 1.f / (1.f + __expf(-s));
    g_xc[idx] = s * sig;
}

__global__ __launch_bounds__(256)
void xproj(const float* __restrict__ Wx) {
    int t = blockIdx.x;
    __shared__ float row[DI];
    for (int i = threadIdx.x; i < DI; i += blockDim.x)
        row[i] = g_xc[t * DI + i];
    __syncthreads();
    int wid = threadIdx.x >> 5, lane = threadIdx.x & 31;
    for (int j = wid; j < 33; j += 8) {
        const float* wr = Wx + j * DI;
        float s = 0.f;
        for (int k = lane; k < DI; k += 32) s += row[k] * wr[k];
        for (int o = 16; o; o >>= 1) s += __shfl_xor_sync(~0u, s, o);
        if (lane == 0) g_xp[t * 33 + j] = s;
    }
}

// ======================= chunked selective scan =======================
// warp = 2 channels x 16 states; 8 chunks of 128 timesteps.
// pass 1: per-chunk scan from h=0; store end state + sum(dt).
__global__ __launch_bounds__(256)
void scan_p1(const float* __restrict__ dt_w, const float* __restrict__ dt_b,
             const float* __restrict__ A_log) {
    int gw = blockIdx.x * 8 + (threadIdx.x >> 5);   // 0..6143
    int lane = threadIdx.x & 31;
    int dpair = gw % (DI / 2);
    int c = gw / (DI / 2);
    int d = dpair * 2 + (lane >> 4);
    int n = lane & 15;

    float Av  = -__expf(A_log[d * DS + n]);
    float dtw = dt_w[d];
    float dtb = dt_b[d];
    float h = 0.f, dts = 0.f;
    int t0 = c * TC;

    for (int tt = 0; tt < TC; tt++) {
        int t = t0 + tt;
        const float* xpr = g_xp + t * 33;
        float dtr = __ldg(xpr);
        float Bn  = __ldg(xpr + 1 + n);
        float xcv = g_xc[t * DI + d];
        float xdt = fmaf(dtr, dtw, dtb);
        float dt  = (xdt > 20.f) ? xdt : log1pf(__expf(xdt));
        float dA  = __expf(dt * Av);
        h = fmaf(dA, h, dt * Bn * xcv);
        dts += dt;
    }
    g_hend[c * (DI * DS) + d * DS + n] = h;
    if (n == 0) g_dts[c * DI + d] = dts;
}

// pass 2: stitch chunk boundary states (serial over 8 chunks, parallel over d,n)
__global__ void scan_p2(const float* __restrict__ A_log) {
    int id = blockIdx.x * blockDim.x + threadIdx.x;   // 0..24575
    if (id >= DI * DS) return;
    int d = id >> 4;
    float Av = -__expf(A_log[id]);
    float h0 = 0.f;
#pragma unroll
    for (int c = 0; c < NC; c++) {
        g_h0[c * (DI * DS) + id] = h0;
        float P = __expf(Av * g_dts[c * DI + d]);
        h0 = fmaf(P, h0, g_hend[c * (DI * DS) + id]);
    }
}

// pass 3: re-run scan with correct h0, emit gated fp16 output into g_a.
__global__ __launch_bounds__(256)
void scan_p3(const float* __restrict__ dt_w, const float* __restrict__ dt_b,
             const float* __restrict__ A_log, const float* __restrict__ Dp) {
    int gw = blockIdx.x * 8 + (threadIdx.x >> 5);
    int lane = threadIdx.x & 31;
    int dpair = gw % (DI / 2);
    int c = gw / (DI / 2);
    int d = dpair * 2 + (lane >> 4);
    int n = lane & 15;

    float Av  = -__expf(A_log[d * DS + n]);
    float dtw = dt_w[d];
    float dtb = dt_b[d];
    float Dv  = Dp[d];
    float h = g_h0[c * (DI * DS) + d * DS + n];
    int t0 = c * TC;

    for (int tt = 0; tt < TC; tt++) {
        int t = t0 + tt;
        const float* xpr = g_xp + t * 33;
        float dtr = __ldg(xpr);
        float Bn  = __ldg(xpr + 1 + n);
        float Cn  = __ldg(xpr + 17 + n);
        float xcv = g_xc[t * DI + d];
        float xdt = fmaf(dtr, dtw, dtb);
        float dt  = (xdt > 20.f) ? xdt : log1pf(__expf(xdt));
        float dA  = __expf(dt * Av);
        h = fmaf(dA, h, dt * Bn * xcv);

        float p = h * Cn;
        p += __shfl_xor_sync(~0u, p, 8);
        p += __shfl_xor_sync(~0u, p, 4);
        p += __shfl_xor_sync(~0u, p, 2);
        p += __shfl_xor_sync(~0u, p, 1);

        if (n == 0) {
            float y = p + xcv * Dv;
            float z = g_xz[t * 2 * DI + DI + d];
            float zs = z / (1.f + __expf(-z));
            g_a[t * DI + d] = __float2half(y * zs);
        }
    }
}

// ======================= host launcher =======================
extern "C" void kernel_launch(void* const* d_in, const int* in_sizes, int n_in,
                              void* d_out, int out_size) {
    const int*   idx      = (const int*)  d_in[0];
    const float* embed    = (const float*)d_in[1];
    const float* norm_w   = (const float*)d_in[2];
    const float* W_in     = (const float*)d_in[3];
    const float* conv_w   = (const float*)d_in[4];
    const float* conv_b   = (const float*)d_in[5];
    const float* W_x      = (const float*)d_in[6];
    const float* dt_w     = (const float*)d_in[7];
    const float* dt_b     = (const float*)d_in[8];
    const float* A_log    = (const float*)d_in[9];
    const float* Dp       = (const float*)d_in[10];
    const float* out_w    = (const float*)d_in[11];
    const float* norm_f_w = (const float*)d_in[12];
    float* out = (float*)d_out;

    float *px, *pxz;
    cudaGetSymbolAddress((void**)&px,  g_x);
    cudaGetSymbolAddress((void**)&pxz, g_xz);
    __half *eb, *wi, *wo, *ac;
    cudaGetSymbolAddress((void**)&eb, g_eb);
    cudaGetSymbolAddress((void**)&wi, g_wi);
    cudaGetSymbolAddress((void**)&wo, g_wo);
    cudaGetSymbolAddress((void**)&ac, g_a);

    static bool attr_set = false;
    if (!attr_set) {
        cudaFuncSetAttribute(gemm_tc, cudaFuncAttributeMaxDynamicSharedMemorySize, GSMEM_B);
        attr_set = true;
    }

    // launches 1-3: weight converts + fused embed+rmsnorm
    {
        int n4 = NL * 2 * DI * DM / 4;
        cvt4<<<(n4 + 255) / 256, 256>>>((const float4*)W_in, (__half2*)wi, n4);
        n4 = NL * DM * DI / 4;
        cvt4<<<(n4 + 255) / 256, 256>>>((const float4*)out_w, (__half2*)wo, n4);
    }
    embed_rms<<<LSEQ, 256>>>(idx, embed, norm_w);   // layer-0 rmsnorm -> g_a (fp16)

    for (int l = 0; l < NL; l++) {
        if (l > 0) rmsnorm_h<<<LSEQ, 256>>>(px, norm_w + l * DM);

        // launch 4 on first layer = gemm_tc (lands in ncu capture slot)
        dim3 g1(2 * DI / 128, LSEQ / 128);
        gemm_tc<<<g1, 256, GSMEM_B>>>(ac, wi + (size_t)l * 2 * DI * DM,
                                      pxz, nullptr, 2 * DI, DM);

        if (l == 0) {  // embed table convert: needed only by final logits GEMM
            int n4 = NV * DM / 4;
            cvt4<<<(n4 + 255) / 256, 256>>>((const float4*)embed, (__half2*)eb, n4);
        }

        conv_silu<<<(LSEQ * DI + 255) / 256, 256>>>(conv_w + l * DI * 4, conv_b + l * DI);
        xproj<<<LSEQ, 256>>>(W_x + l * 33 * DI);

        scan_p1<<<(DI / 2) * NC / 8, 256>>>(dt_w + l * DI, dt_b + l * DI, A_log + l * DI * DS);
        scan_p2<<<(DI * DS + 255) / 256, 256>>>(A_log + l * DI * DS);
        scan_p3<<<(DI / 2) * NC / 8, 256>>>(dt_w + l * DI, dt_b + l * DI,
                                            A_log + l * DI * DS, Dp + l * DI);

        dim3 g2(DM / 128, LSEQ / 128);
        gemm_tc<<<g2, 256, GSMEM_B>>>(ac, wo + (size_t)l * DM * DI,
                                      px, px, DM, DI);
    }

    rmsnorm_h<<<LSEQ, 256>>>(px, norm_f_w);
    dim3 g3(NV / 128, LSEQ / 128);
    gemm_tc<<<g3, 256, GSMEM_B>>>(ac, eb, out, nullptr, NV, DM);
}

// round 15
// speedup vs baseline: 2.4925x; 1.0862x over previous
#include <cuda_runtime.h>
#include <cuda_fp16.h>
#include <stdint.h>

#define DM 768
#define DI 1536
#define DS 16
#define LSEQ 1024
#define NL 4
#define NV 32000
#define NC 8
#define TC (LSEQ / NC)

// ---------------- fp32 scratch ----------------
__device__ float g_x [LSEQ * DM];        // residual stream
__device__ float g_xz[LSEQ * 2 * DI];    // in-proj output (x_ssm | z)
__device__ float g_xc[LSEQ * DI];        // conv+silu output
__device__ float g_xp[LSEQ * 33];        // x-proj output (dt_r | B | C)
// scan chunk scratch
__device__ float g_hend[NC * DI * DS];
__device__ float g_h0  [NC * DI * DS];
__device__ float g_dts [NC * DI];

// ---------------- fp16 operands ----------------
__device__ __half g_eb[NV * DM];
__device__ __half g_wi[NL * 2 * DI * DM];
__device__ __half g_wo[NL * DM * DI];
__device__ __half g_a [LSEQ * DI];       // GEMM A operand

// ======================= helpers =======================
__device__ __forceinline__ uint32_t smem_u32(const void* p) {
    uint32_t a;
    asm("{ .reg .u64 t; cvta.to.shared.u64 t, %1; cvt.u32.u64 %0, t; }" : "=r"(a) : "l"(p));
    return a;
}
__device__ __forceinline__ void cp_async16(uint32_t saddr, const void* gaddr) {
    asm volatile("cp.async.cg.shared.global [%0], [%1], 16;" :: "r"(saddr), "l"(gaddr));
}
__device__ __forceinline__ void cp_commit() {
    asm volatile("cp.async.commit_group;" ::: "memory");
}
__device__ __forceinline__ void cp_wait1() {
    asm volatile("cp.async.wait_group 1;" ::: "memory");
}
__device__ __forceinline__ void mma16816(float* c, const uint32_t* a, const uint32_t* b) {
    asm volatile("mma.sync.aligned.m16n8k16.row.col.f32.f16.f16.f32 "
                 "{%0,%1,%2,%3}, {%4,%5,%6,%7}, {%8,%9}, {%0,%1,%2,%3};"
                 : "+f"(c[0]), "+f"(c[1]), "+f"(c[2]), "+f"(c[3])
                 : "r"(a[0]), "r"(a[1]), "r"(a[2]), "r"(a[3]), "r"(b[0]), "r"(b[1]));
}
__device__ __forceinline__ void ldsm4(uint32_t& r0, uint32_t& r1, uint32_t& r2, uint32_t& r3,
                                      uint32_t saddr) {
    asm volatile("ldmatrix.sync.aligned.m8n8.x4.shared.b16 {%0,%1,%2,%3}, [%4];"
                 : "=r"(r0), "=r"(r1), "=r"(r2), "=r"(r3) : "r"(saddr));
}

// ======================= convert fp32 -> fp16 =======================
__global__ void cvt4(const float4* __restrict__ src, __half2* __restrict__ dst, int n4) {
    int i = blockIdx.x * blockDim.x + threadIdx.x;
    if (i >= n4) return;
    float4 v = src[i];
    dst[2 * i]     = __floats2half2_rn(v.x, v.y);
    dst[2 * i + 1] = __floats2half2_rn(v.z, v.w);
}

// ======================= mma.sync GEMM (fp16, fp32 acc) =======================
// C[M,N] (+=) A[M,K] @ B[N,K]^T (+ add).
// 128x128 tile, K-stage 32, 3-buffer cp.async ring (prefetch depth 2), occ 2.
// blockIdx.z = split-K index over chunks of `kchunk`; if gridDim.z > 1 the
// epilogue atomically accumulates into C (C must already hold the residual).
#define ROWP 40                       // padded row stride (elements); 80 bytes
#define OPSZ (128 * ROWP)
#define STAGE_E (2 * OPSZ)            // A, B
#define NSTG 3
#define GSMEM_B (NSTG * STAGE_E * 2)  // 61440 bytes

__global__ __launch_bounds__(256, 2)
void gemm_tc(const __half* __restrict__ A, const __half* __restrict__ B,
             float* __restrict__ C, const float* __restrict__ add,
             int N, int K, int kchunk) {
    extern __shared__ __half sm[];
    uint32_t sb = smem_u32(sm);
    int tid = threadIdx.x;
    int wid = tid >> 5, lane = tid & 31;
    int warp_m = wid >> 2, warp_n = wid & 3;     // 2 x 4
    int quad = lane >> 3, lr = lane & 7;
    int m0 = blockIdx.y * 128, n0 = blockIdx.x * 128;
    int kbase = blockIdx.z * kchunk;

    const __half* gA = A + (size_t)m0 * K + kbase;
    const __half* gB = B + (size_t)n0 * K + kbase;
    int nst = kchunk >> 5;

    auto load_stage = [&](int ks) {
        int k0 = ks << 5;
        int buf = ks % NSTG;
        uint32_t sbase = sb + (uint32_t)buf * (STAGE_E * 2);
#pragma unroll
        for (int c = 0; c < 4; c++) {
            int ch  = tid + c * 256;          // 0..1023
            int op  = ch >> 9;                // 0=A, 1=B
            int idx = ch & 511;
            int row = idx >> 2, q = idx & 3;
            const __half* g = (op == 0) ? gA : gB;
            cp_async16(sbase + (uint32_t)(op * OPSZ + row * ROWP + q * 8) * 2,
                       g + (size_t)row * K + k0 + q * 8);
        }
    };

    int rA = (quad & 1) * 8 + lr, cAo = (quad >> 1) * 8;
    int rB = (quad >> 1) * 8 + lr, cBo = (quad & 1) * 8;

    float acc[4][4][4] = {};

    load_stage(0); cp_commit();
    load_stage(1); cp_commit();

    for (int ks = 0; ks < nst; ks++) {
        cp_wait1();
        __syncthreads();
        // all threads finished compute(ks-1); buffer (ks+2)%3 is free
        if (ks + 2 < nst) { load_stage(ks + 2); }
        cp_commit();

        uint32_t st = sb + (uint32_t)(ks % NSTG) * (STAGE_E * 2);
        uint32_t aS = st;
        uint32_t bS = st + OPSZ * 2;

#pragma unroll
        for (int kk = 0; kk < 32; kk += 16) {
            uint32_t af[4][4], bf[4][2];
#pragma unroll
            for (int mt = 0; mt < 4; mt++) {
                uint32_t off = (uint32_t)((warp_m * 64 + mt * 16 + rA) * ROWP + kk + cAo) * 2;
                ldsm4(af[mt][0], af[mt][1], af[mt][2], af[mt][3], aS + off);
            }
#pragma unroll
            for (int p = 0; p < 2; p++) {
                uint32_t off = (uint32_t)((warp_n * 32 + p * 16 + rB) * ROWP + kk + cBo) * 2;
                ldsm4(bf[2 * p][0], bf[2 * p][1], bf[2 * p + 1][0], bf[2 * p + 1][1], bS + off);
            }
#pragma unroll
            for (int mt = 0; mt < 4; mt++)
#pragma unroll
                for (int nt = 0; nt < 4; nt++) mma16816(acc[mt][nt], af[mt], bf[nt]);
        }
    }

    __syncthreads();
    int g = lane >> 2, tg = lane & 3;
    bool atom = (gridDim.z > 1);
#pragma unroll
    for (int mt = 0; mt < 4; mt++)
#pragma unroll
        for (int nt = 0; nt < 4; nt++) {
            int m = m0 + warp_m * 64 + mt * 16 + g;
            int n = n0 + warp_n * 32 + nt * 8 + tg * 2;
            float* c = acc[mt][nt];
            size_t o0 = (size_t)m * N + n;
            size_t o1 = (size_t)(m + 8) * N + n;
            if (atom) {
                atomicAdd(C + o0, c[0]);     atomicAdd(C + o0 + 1, c[1]);
                atomicAdd(C + o1, c[2]);     atomicAdd(C + o1 + 1, c[3]);
            } else {
                if (add) {
                    c[0] += add[o0]; c[1] += add[o0 + 1];
                    c[2] += add[o1]; c[3] += add[o1 + 1];
                }
                *(float2*)(C + o0) = make_float2(c[0], c[1]);
                *(float2*)(C + o1) = make_float2(c[2], c[3]);
            }
        }
}

// ======================= fused embed + rmsnorm (layer 0) =======================
__global__ void embed_rms(const int* __restrict__ idx, const float* __restrict__ embed,
                          const float* __restrict__ w) {
    int t = blockIdx.x;
    int row = idx[t];
    const float* src = embed + (size_t)row * DM;
    __shared__ float red[32];
    float s = 0.f;
    for (int i = threadIdx.x; i < DM; i += blockDim.x) {
        float v = src[i];
        g_x[t * DM + i] = v;
        s += v * v;
    }
    for (int o = 16; o; o >>= 1) s += __shfl_xor_sync(~0u, s, o);
    if ((threadIdx.x & 31) == 0) red[threadIdx.x >> 5] = s;
    __syncthreads();
    if (threadIdx.x < 32) {
        float v = (threadIdx.x < (blockDim.x >> 5)) ? red[threadIdx.x] : 0.f;
        for (int o = 16; o; o >>= 1) v += __shfl_xor_sync(~0u, v, o);
        if (threadIdx.x == 0) red[0] = rsqrtf(v / (float)DM + 1e-5f);
    }
    __syncthreads();
    float inv = red[0];
    for (int i = threadIdx.x; i < DM; i += blockDim.x)
        g_a[t * DM + i] = __float2half(src[i] * inv * w[i]);
}

// rmsnorm from g_x -> fp16 g_a
__global__ void rmsnorm_h(const float* __restrict__ in, const float* __restrict__ w) {
    int t = blockIdx.x;
    __shared__ float red[32];
    float s = 0.f;
    for (int i = threadIdx.x; i < DM; i += blockDim.x) {
        float v = in[t * DM + i];
        s += v * v;
    }
    for (int o = 16; o; o >>= 1) s += __shfl_xor_sync(~0u, s, o);
    if ((threadIdx.x & 31) == 0) red[threadIdx.x >> 5] = s;
    __syncthreads();
    if (threadIdx.x < 32) {
        float v = (threadIdx.x < (blockDim.x >> 5)) ? red[threadIdx.x] : 0.f;
        for (int o = 16; o; o >>= 1) v += __shfl_xor_sync(~0u, v, o);
        if (threadIdx.x == 0) red[0] = rsqrtf(v / (float)DM + 1e-5f);
    }
    __syncthreads();
    float inv = red[0];
    for (int i = threadIdx.x; i < DM; i += blockDim.x)
        g_a[t * DM + i] = __float2half(in[t * DM + i] * inv * w[i]);
}

// ======================= conv / xproj =======================
__global__ void conv_silu(const float* __restrict__ cw, const float* __restrict__ cb) {
    int idx = blockIdx.x * blockDim.x + threadIdx.x;
    if (idx >= LSEQ * DI) return;
    int d = idx % DI, t = idx / DI;
    float s = cb[d];
#pragma unroll
    for (int j = 0; j < 4; j++) {
        int tt = t - 3 + j;
        if (tt >= 0) s += g_xz[tt * (2 * DI) + d] * cw[d * 4 + j];
    }
    float sig = 1.f / (1.f + __expf(-s));
    g_xc[idx] = s * sig;
}

__global__ __launch_bounds__(256)
void xproj(const float* __restrict__ Wx) {
    int t = blockIdx.x;
    __shared__ float row[DI];
    for (int i = threadIdx.x; i < DI; i += blockDim.x)
        row[i] = g_xc[t * DI + i];
    __syncthreads();
    int wid = threadIdx.x >> 5, lane = threadIdx.x & 31;
    for (int j = wid; j < 33; j += 8) {
        const float* wr = Wx + j * DI;
        float s = 0.f;
        for (int k = lane; k < DI; k += 32) s += row[k] * wr[k];
        for (int o = 16; o; o >>= 1) s += __shfl_xor_sync(~0u, s, o);
        if (lane == 0) g_xp[t * 33 + j] = s;
    }
}

// ======================= chunked selective scan =======================
__global__ __launch_bounds__(256)
void scan_p1(const float* __restrict__ dt_w, const float* __restrict__ dt_b,
             const float* __restrict__ A_log) {
    int gw = blockIdx.x * 8 + (threadIdx.x >> 5);   // 0..6143
    int lane = threadIdx.x & 31;
    int dpair = gw % (DI / 2);
    int c = gw / (DI / 2);
    int d = dpair * 2 + (lane >> 4);
    int n = lane & 15;

    float Av  = -__expf(A_log[d * DS + n]);
    float dtw = dt_w[d];
    float dtb = dt_b[d];
    float h = 0.f, dts = 0.f;
    int t0 = c * TC;

    for (int tt = 0; tt < TC; tt++) {
        int t = t0 + tt;
        const float* xpr = g_xp + t * 33;
        float dtr = __ldg(xpr);
        float Bn  = __ldg(xpr + 1 + n);
        float xcv = g_xc[t * DI + d];
        float xdt = fmaf(dtr, dtw, dtb);
        float dt  = (xdt > 20.f) ? xdt : log1pf(__expf(xdt));
        float dA  = __expf(dt * Av);
        h = fmaf(dA, h, dt * Bn * xcv);
        dts += dt;
    }
    g_hend[c * (DI * DS) + d * DS + n] = h;
    if (n == 0) g_dts[c * DI + d] = dts;
}

__global__ void scan_p2(const float* __restrict__ A_log) {
    int id = blockIdx.x * blockDim.x + threadIdx.x;   // 0..24575
    if (id >= DI * DS) return;
    int d = id >> 4;
    float Av = -__expf(A_log[id]);
    float h0 = 0.f;
#pragma unroll
    for (int c = 0; c < NC; c++) {
        g_h0[c * (DI * DS) + id] = h0;
        float P = __expf(Av * g_dts[c * DI + d]);
        h0 = fmaf(P, h0, g_hend[c * (DI * DS) + id]);
    }
}

__global__ __launch_bounds__(256)
void scan_p3(const float* __restrict__ dt_w, const float* __restrict__ dt_b,
             const float* __restrict__ A_log, const float* __restrict__ Dp) {
    int gw = blockIdx.x * 8 + (threadIdx.x >> 5);
    int lane = threadIdx.x & 31;
    int dpair = gw % (DI / 2);
    int c = gw / (DI / 2);
    int d = dpair * 2 + (lane >> 4);
    int n = lane & 15;

    float Av  = -__expf(A_log[d * DS + n]);
    float dtw = dt_w[d];
    float dtb = dt_b[d];
    float Dv  = Dp[d];
    float h = g_h0[c * (DI * DS) + d * DS + n];
    int t0 = c * TC;

    for (int tt = 0; tt < TC; tt++) {
        int t = t0 + tt;
        const float* xpr = g_xp + t * 33;
        float dtr = __ldg(xpr);
        float Bn  = __ldg(xpr + 1 + n);
        float Cn  = __ldg(xpr + 17 + n);
        float xcv = g_xc[t * DI + d];
        float xdt = fmaf(dtr, dtw, dtb);
        float dt  = (xdt > 20.f) ? xdt : log1pf(__expf(xdt));
        float dA  = __expf(dt * Av);
        h = fmaf(dA, h, dt * Bn * xcv);

        float p = h * Cn;
        p += __shfl_xor_sync(~0u, p, 8);
        p += __shfl_xor_sync(~0u, p, 4);
        p += __shfl_xor_sync(~0u, p, 2);
        p += __shfl_xor_sync(~0u, p, 1);

        if (n == 0) {
            float y = p + xcv * Dv;
            float z = g_xz[t * 2 * DI + DI + d];
            float zs = z / (1.f + __expf(-z));
            g_a[t * DI + d] = __float2half(y * zs);
        }
    }
}

// ======================= host launcher =======================
extern "C" void kernel_launch(void* const* d_in, const int* in_sizes, int n_in,
                              void* d_out, int out_size) {
    const int*   idx      = (const int*)  d_in[0];
    const float* embed    = (const float*)d_in[1];
    const float* norm_w   = (const float*)d_in[2];
    const float* W_in     = (const float*)d_in[3];
    const float* conv_w   = (const float*)d_in[4];
    const float* conv_b   = (const float*)d_in[5];
    const float* W_x      = (const float*)d_in[6];
    const float* dt_w     = (const float*)d_in[7];
    const float* dt_b     = (const float*)d_in[8];
    const float* A_log    = (const float*)d_in[9];
    const float* Dp       = (const float*)d_in[10];
    const float* out_w    = (const float*)d_in[11];
    const float* norm_f_w = (const float*)d_in[12];
    float* out = (float*)d_out;

    float *px, *pxz;
    cudaGetSymbolAddress((void**)&px,  g_x);
    cudaGetSymbolAddress((void**)&pxz, g_xz);
    __half *eb, *wi, *wo, *ac;
    cudaGetSymbolAddress((void**)&eb, g_eb);
    cudaGetSymbolAddress((void**)&wi, g_wi);
    cudaGetSymbolAddress((void**)&wo, g_wo);
    cudaGetSymbolAddress((void**)&ac, g_a);

    static bool attr_set = false;
    if (!attr_set) {
        cudaFuncSetAttribute(gemm_tc, cudaFuncAttributeMaxDynamicSharedMemorySize, GSMEM_B);
        attr_set = true;
    }

    {
        int n4 = NL * 2 * DI * DM / 4;
        cvt4<<<(n4 + 255) / 256, 256>>>((const float4*)W_in, (__half2*)wi, n4);
        n4 = NL * DM * DI / 4;
        cvt4<<<(n4 + 255) / 256, 256>>>((const float4*)out_w, (__half2*)wo, n4);
    }
    embed_rms<<<LSEQ, 256>>>(idx, embed, norm_w);

    for (int l = 0; l < NL; l++) {
        if (l > 0) rmsnorm_h<<<LSEQ, 256>>>(px, norm_w + l * DM);

        // in-proj (lands in ncu capture slot on layer 0)
        dim3 g1(2 * DI / 128, LSEQ / 128, 1);
        gemm_tc<<<g1, 256, GSMEM_B>>>(ac, wi + (size_t)l * 2 * DI * DM,
                                      pxz, nullptr, 2 * DI, DM, DM);

        if (l == 0) {
            int n4 = NV * DM / 4;
            cvt4<<<(n4 + 255) / 256, 256>>>((const float4*)embed, (__half2*)eb, n4);
        }

        conv_silu<<<(LSEQ * DI + 255) / 256, 256>>>(conv_w + l * DI * 4, conv_b + l * DI);
        xproj<<<LSEQ, 256>>>(W_x + l * 33 * DI);

        scan_p1<<<(DI / 2) * NC / 8, 256>>>(dt_w + l * DI, dt_b + l * DI, A_log + l * DI * DS);
        scan_p2<<<(DI * DS + 255) / 256, 256>>>(A_log + l * DI * DS);
        scan_p3<<<(DI / 2) * NC / 8, 256>>>(dt_w + l * DI, dt_b + l * DI,
                                            A_log + l * DI * DS, Dp + l * DI);

        // out-proj: split-K=3, atomic accumulate onto residual stream px
        dim3 g2(DM / 128, LSEQ / 128, 3);
        gemm_tc<<<g2, 256, GSMEM_B>>>(ac, wo + (size_t)l * DM * DI,
                                      px, nullptr, DM, DI, DI / 3);
    }

    rmsnorm_h<<<LSEQ, 256>>>(px, norm_f_w);
    dim3 g3(NV / 128, LSEQ / 128, 1);
    gemm_tc<<<g3, 256, GSMEM_B>>>(ac, eb, out, nullptr, NV, DM, DM);
}